// round 10
// baseline (speedup 1.0000x reference)
#include <cuda_runtime.h>
#include <cstdint>

#define BB 2
#define TT 4096
#define CC 2048
#define NT (BB*TT)   // 8192 tokens

typedef unsigned long long ull;

// interleaved scan input: [tok][h][f][64], f: 0=r, 1=k, 2=wd, 3=v  (256MB)
__device__ float g_seq[(size_t)NT*32*4*64];

// ---------------- packed f32x2 helpers ----------------
__device__ __forceinline__ ull pk(float lo, float hi){
    ull r; asm("mov.b64 %0,{%1,%2};" : "=l"(r) : "f"(lo), "f"(hi)); return r;
}
__device__ __forceinline__ ull dup(float x){
    ull r; asm("mov.b64 %0,{%1,%1};" : "=l"(r) : "f"(x)); return r;
}
__device__ __forceinline__ float2 up2(ull a){
    float2 f; asm("mov.b64 {%0,%1},%2;" : "=f"(f.x), "=f"(f.y) : "l"(a)); return f;
}
__device__ __forceinline__ ull fma2(ull a, ull b, ull c){
    ull d; asm("fma.rn.f32x2 %0,%1,%2,%3;" : "=l"(d) : "l"(a), "l"(b), "l"(c)); return d;
}
__device__ __forceinline__ ull mul2(ull a, ull b){
    ull d; asm("mul.rn.f32x2 %0,%1,%2;" : "=l"(d) : "l"(a), "l"(b)); return d;
}
__device__ __forceinline__ void cpa16(uint32_t dst, const void* src){
    asm volatile("cp.async.cg.shared.global [%0],[%1],16;\n" :: "r"(dst), "l"(src) : "memory");
}
__device__ __forceinline__ void cpa_commit(){
    asm volatile("cp.async.commit_group;\n" ::: "memory");
}
__device__ __forceinline__ void cpa_wait0(){
    asm volatile("cp.async.wait_group 0;\n" ::: "memory");
}

// ---------------- k_fused shared layout (float offsets) ----------------
#define OFF_XXX 0            // [64][128]     8192
#define OFF_W2  8192         // [128][128]   16384  -> 24576
#define OFF_DW1 24576        // 2 x [128][68] 17408 -> 41984
#define OFF_XW  41984        // [64][132]     8448  -> 50432
#define OFF_A   50432        // [32][68]      2176  -> 52608
#define OFF_B   52608        // [32][128]     4096  -> 56704
// phase C reuse: D1 at 0 ([64][68] 4352), DW2 at 8192 ([64][128] 8192)
#define SMEM_F 56704
#define SMEM_BYTES (SMEM_F*4)

// =====================================================================
// k_fused: token-shift mix + decay LoRA. 64 tokens/block, 512 threads,
// grid 128. tx = tid&15 (8 output cols), ty = tid>>4 in 0..31 (2 tokens).
// =====================================================================
__global__ __launch_bounds__(512, 1) void k_fused(
    const float* __restrict__ hidden, const float* __restrict__ attn_x,
    const float* __restrict__ maa_x,  const float* __restrict__ maa_w,
    const float* __restrict__ maa_k,  const float* __restrict__ maa_v,
    const float* __restrict__ maa_r,  const float* __restrict__ w1,
    const float* __restrict__ w2,     const float* __restrict__ dw1,
    const float* __restrict__ dw2,    const float* __restrict__ tdecay)
{
    extern __shared__ float sm[];
    const int tid = threadIdx.x;
    const int tx = tid & 15, ty = tid >> 4;   // ty in 0..31
    const int bt0 = blockIdx.x * 64;

    const uint32_t smb = (uint32_t)__cvta_generic_to_shared(sm);

    // stage w2 + dw1 chunk via cp.async (one commit group)
    auto stage_wd = [&](int c0, int buf){
        #pragma unroll
        for (int l = 0; l < 8; l++){
            int i = tid + l*512;                // 0..4095 float4s
            int row = i >> 5, c4 = i & 31;
            cpa16(smb + (uint32_t)(OFF_W2 + row*128 + c4*4)*4u,
                  w2 + (size_t)row*CC + c0 + c4*4);
        }
        #pragma unroll
        for (int l = 0; l < 4; l++){
            int i = tid + l*512;                // 0..2047 float4s
            int row = i >> 4, c4 = i & 15;
            cpa16(smb + (uint32_t)(OFF_DW1 + buf*8704 + row*68 + c4*4)*4u,
                  dw1 + (size_t)(c0 + row)*64 + c4*4);
        }
        cpa_commit();
    };

    stage_wd(0, 0);

    // ================= Phase A: xxx = tanh(z @ W1[:,:128]) =================
    {
        float* As = sm + OFF_A;
        float* Bs = sm + OFF_B;
        float rx[4], rp[4], rm[4], rb[8];

        auto prefA = [&](int kc){
            #pragma unroll
            for (int l = 0; l < 4; l++){
                int i = tid + l*512; int kk = i & 31, tl = i >> 5;
                int tok = bt0 + tl; int c = kc + kk;
                rx[l] = hidden[(size_t)tok*CC + c];
                rp[l] = ((tok & (TT-1)) == 0) ? attn_x[(size_t)(tok >> 12)*CC + c]
                                              : hidden[(size_t)(tok-1)*CC + c];
                rm[l] = maa_x[c];
            }
            #pragma unroll
            for (int l = 0; l < 8; l++){
                int i = tid + l*512; int kk = i >> 7, n = i & 127;
                rb[l] = w1[(size_t)(kc+kk)*160 + n];
            }
        };

        ull acc[2][4];
        #pragma unroll
        for (int i = 0; i < 2; i++)
            #pragma unroll
            for (int j = 0; j < 4; j++) acc[i][j] = 0ull;

        prefA(0);
        for (int kc = 0; kc < CC; kc += 32){
            #pragma unroll
            for (int l = 0; l < 4; l++){
                int i = tid + l*512; int kk = i & 31, tl = i >> 5;
                As[kk*68 + tl] = rx[l] + (rp[l] - rx[l])*rm[l];
            }
            #pragma unroll
            for (int l = 0; l < 8; l++){
                int i = tid + l*512; int kk = i >> 7, n = i & 127;
                Bs[kk*128 + n] = rb[l];
            }
            __syncthreads();
            if (kc + 32 < CC) prefA(kc + 32);
            #pragma unroll
            for (int kk = 0; kk < 32; kk++){
                float2 av = *(const float2*)&As[kk*68 + ty*2];
                ulonglong2 b01 = *(const ulonglong2*)&Bs[kk*128 + tx*8];
                ulonglong2 b23 = *(const ulonglong2*)&Bs[kk*128 + tx*8 + 4];
                ull bp[4] = {b01.x, b01.y, b23.x, b23.y};
                float aa[2] = {av.x, av.y};
                #pragma unroll
                for (int i = 0; i < 2; i++){
                    ull ad = dup(aa[i]);
                    #pragma unroll
                    for (int j = 0; j < 4; j++) acc[i][j] = fma2(ad, bp[j], acc[i][j]);
                }
            }
            __syncthreads();
        }
        #pragma unroll
        for (int i = 0; i < 2; i++){
            #pragma unroll
            for (int jp = 0; jp < 4; jp++){
                float2 f = up2(acc[i][jp]);
                int r = (ty*2 + i)*128 + tx*8 + 2*jp;
                sm[OFF_XXX + r]   = tanhf(f.x);
                sm[OFF_XXX + r+1] = tanhf(f.y);
            }
        }
    }

    // ================= Phase B =================
    float* xxx_s = sm + OFF_XXX;
    float* w2_s  = sm + OFF_W2;
    float* xw_s  = sm + OFF_XW;

    ull acc_d1[2][2];
    #pragma unroll
    for (int i = 0; i < 2; i++){ acc_d1[i][0] = 0ull; acc_d1[i][1] = 0ull; }

    for (int c0 = 0; c0 < CC; c0 += 128){
        const int cbuf = (c0 >> 7) & 1;
        cpa_wait0();
        __syncthreads();           // w2/dw1 ready; also covers xxx after phase A

        const int cb = c0 + tx*8;
        const int hh = cb >> 6, lmm = cb & 63;

        // x / diff operands -> registers
        float xr[2][8], dr[2][8];
        #pragma unroll
        for (int i = 0; i < 2; i++){
            const int tok = bt0 + ty*2 + i;
            const size_t gofs = (size_t)tok*CC + cb;
            float4 xa = *(const float4*)&hidden[gofs];
            float4 xb = *(const float4*)&hidden[gofs + 4];
            const float* prow = ((tok & (TT-1)) == 0) ? (attn_x + (size_t)(tok >> 12)*CC)
                                                      : (hidden + (size_t)(tok-1)*CC);
            float4 pa = *(const float4*)&prow[cb];
            float4 pb = *(const float4*)&prow[cb + 4];
            xr[i][0]=xa.x; xr[i][1]=xa.y; xr[i][2]=xa.z; xr[i][3]=xa.w;
            xr[i][4]=xb.x; xr[i][5]=xb.y; xr[i][6]=xb.z; xr[i][7]=xb.w;
            dr[i][0]=pa.x-xa.x; dr[i][1]=pa.y-xa.y; dr[i][2]=pa.z-xa.z; dr[i][3]=pa.w-xa.w;
            dr[i][4]=pb.x-xb.x; dr[i][5]=pb.y-xb.y; dr[i][6]=pb.z-xb.z; dr[i][7]=pb.w-xb.w;
        }

        #pragma unroll
        for (int f = 0; f < 4; f++){
            ull macc[2][4];
            #pragma unroll
            for (int i = 0; i < 2; i++)
                #pragma unroll
                for (int j = 0; j < 4; j++) macc[i][j] = 0ull;

            #pragma unroll
            for (int kk = 0; kk < 32; kk++){
                ulonglong2 wa = *(const ulonglong2*)&w2_s[(f*32+kk)*128 + tx*8];
                ulonglong2 wb = *(const ulonglong2*)&w2_s[(f*32+kk)*128 + tx*8 + 4];
                ull bp[4] = {wa.x, wa.y, wb.x, wb.y};
                #pragma unroll
                for (int i = 0; i < 2; i++){
                    ull ad = dup(xxx_s[(ty*2 + i)*128 + f*32 + kk]);
                    #pragma unroll
                    for (int j = 0; j < 4; j++) macc[i][j] = fma2(ad, bp[j], macc[i][j]);
                }
            }
            const float* maaf = (f==0) ? maa_w : (f==1) ? maa_k : (f==2) ? maa_v : maa_r;
            float4 ma = *(const float4*)&maaf[cb];
            float4 mb = *(const float4*)&maaf[cb + 4];
            float mmv[8] = {ma.x,ma.y,ma.z,ma.w,mb.x,mb.y,mb.z,mb.w};
            const int slot = (f==1) ? 1 : (f==2) ? 3 : 0;
            #pragma unroll
            for (int i = 0; i < 2; i++){
                const int tl = ty*2 + i;
                float mq[8];
                #pragma unroll
                for (int jp = 0; jp < 4; jp++){
                    float2 q = up2(macc[i][jp]);
                    mq[2*jp] = q.x; mq[2*jp+1] = q.y;
                }
                float o[8];
                #pragma unroll
                for (int e = 0; e < 8; e++) o[e] = xr[i][e] + dr[i][e]*(mmv[e] + mq[e]);
                if (f == 0){
                    *(float4*)&xw_s[tl*132 + tx*8]     = make_float4(o[0],o[1],o[2],o[3]);
                    *(float4*)&xw_s[tl*132 + tx*8 + 4] = make_float4(o[4],o[5],o[6],o[7]);
                } else {
                    float* dst = &g_seq[((size_t)(bt0 + tl)*32 + hh)*256 + slot*64 + lmm];
                    *(float4*)&dst[0] = make_float4(o[0],o[1],o[2],o[3]);
                    *(float4*)&dst[4] = make_float4(o[4],o[5],o[6],o[7]);
                }
            }
        }
        __syncthreads();           // xw_s complete; w2/dw1 fully consumed

        if (c0 + 128 < CC) stage_wd(c0 + 128, cbuf ^ 1);
        else               cpa_commit();

        const float* dw1c = sm + OFF_DW1 + cbuf*8704;
        #pragma unroll 2
        for (int kk = 0; kk < 128; kk++){
            ulonglong2 bp = *(const ulonglong2*)&dw1c[kk*68 + tx*4];
            #pragma unroll
            for (int i = 0; i < 2; i++){
                ull ad = dup(xw_s[(ty*2 + i)*132 + kk]);
                acc_d1[i][0] = fma2(ad, bp.x, acc_d1[i][0]);
                acc_d1[i][1] = fma2(ad, bp.y, acc_d1[i][1]);
            }
        }
    }
    cpa_wait0();
    __syncthreads();

    // ================= Phase C: wd = exp(-exp(td + tanh(d1) @ dw2)) =================
    float* d1_s  = sm;             // [64][68]
    float* dw2_s = sm + 8192;      // [64][128]
    #pragma unroll
    for (int i = 0; i < 2; i++){
        float2 e0 = up2(acc_d1[i][0]);
        float2 e1 = up2(acc_d1[i][1]);
        int r = (ty*2 + i)*68 + tx*4;
        d1_s[r]   = tanhf(e0.x);
        d1_s[r+1] = tanhf(e0.y);
        d1_s[r+2] = tanhf(e1.x);
        d1_s[r+3] = tanhf(e1.y);
    }
    __syncthreads();

    for (int c0 = 0; c0 < CC; c0 += 128){
        #pragma unroll
        for (int l = 0; l < 16; l++){
            int i = tid + l*512;
            dw2_s[i] = dw2[(size_t)(i >> 7)*CC + c0 + (i & 127)];
        }
        __syncthreads();
        ull wacc[2][4];
        #pragma unroll
        for (int i = 0; i < 2; i++)
            #pragma unroll
            for (int j = 0; j < 4; j++) wacc[i][j] = 0ull;
        #pragma unroll 4
        for (int jj = 0; jj < 64; jj++){
            ulonglong2 wa = *(const ulonglong2*)&dw2_s[jj*128 + tx*8];
            ulonglong2 wb = *(const ulonglong2*)&dw2_s[jj*128 + tx*8 + 4];
            #pragma unroll
            for (int i = 0; i < 2; i++){
                ull ad = dup(d1_s[(ty*2 + i)*68 + jj]);
                wacc[i][0] = fma2(ad, wa.x, wacc[i][0]);
                wacc[i][1] = fma2(ad, wa.y, wacc[i][1]);
                wacc[i][2] = fma2(ad, wb.x, wacc[i][2]);
                wacc[i][3] = fma2(ad, wb.y, wacc[i][3]);
            }
        }
        const int cb = c0 + tx*8;
        const int hh = cb >> 6, lmm = cb & 63;
        float4 t0 = *(const float4*)&tdecay[cb];
        float4 t1 = *(const float4*)&tdecay[cb + 4];
        float td[8] = {t0.x,t0.y,t0.z,t0.w,t1.x,t1.y,t1.z,t1.w};
        #pragma unroll
        for (int i = 0; i < 2; i++){
            const int tl = ty*2 + i;
            float mq[8];
            #pragma unroll
            for (int jp = 0; jp < 4; jp++){
                float2 q = up2(wacc[i][jp]);
                mq[2*jp] = q.x; mq[2*jp+1] = q.y;
            }
            float o[8];
            #pragma unroll
            for (int e = 0; e < 8; e++) o[e] = expf(-expf(td[e] + mq[e]));
            float* dst = &g_seq[((size_t)(bt0 + tl)*32 + hh)*256 + 128 + lmm];
            *(float4*)&dst[0] = make_float4(o[0],o[1],o[2],o[3]);
            *(float4*)&dst[4] = make_float4(o[4],o[5],o[6],o[7]);
        }
        __syncthreads();
    }
}

// =====================================================================
// k_scan: 128 blocks = (b, h, m-half). 512 threads:
//   lm = tid&31 (m within half), q = tid>>5 (16 n-quartets). 2 f32x2
//   state pairs/thread. cp.async ring 32 steps, groups of 16.
// =====================================================================
#define SCAN_SMEM_BYTES ((32*256 + 16*512)*4)   // ring 32KB + partial 32KB

__global__ __launch_bounds__(512) void k_scan(
    const float* __restrict__ attn_kv, const float* __restrict__ faaaa,
    float* __restrict__ out)
{
    extern __shared__ float ssm[];
    float* ring    = ssm;              // [32][256]
    float* partial = ssm + 32*256;     // [16][512]

    const int tid = threadIdx.x;
    const int bid = blockIdx.x;
    const int b = bid >> 6, h = (bid >> 1) & 31, half = bid & 1;
    const int lm = tid & 31, q = tid >> 5;        // q in 0..15
    const int mg = half*32 + lm;

    const ull ud = dup(faaaa[h]);

    ull s2[2];
    const float* kvp = attn_kv + ((size_t)(b*32 + h))*4096;
    #pragma unroll
    for (int j = 0; j < 2; j++){
        int n0 = q*4 + 2*j;
        s2[j] = pk(kvp[n0*64 + mg], kvp[(n0+1)*64 + mg]);
    }

    const float4* srcb = (const float4*)g_seq + ((size_t)b*TT)*2048 + h*64;
    const uint32_t rbase = (uint32_t)__cvta_generic_to_shared(ring);

    // stage one 16-step group: 1024 float4s / 512 threads = 2 each
    auto stage = [&](int g16){
        #pragma unroll
        for (int l = 0; l < 2; l++){
            int i = tid + l*512;              // 0..1023
            int t = g16*16 + (i >> 6), o = i & 63;
            cpa16(rbase + (uint32_t)((t & 31)*1024 + o*16), srcb + (size_t)t*2048 + o);
        }
        cpa_commit();
    };

    stage(0);
    stage(1);

    const size_t obase = (size_t)b*TT*CC + h*64 + half*32;
    const int nb = q*4;

    for (int g = 0; g < TT/16; g++){
        asm volatile("cp.async.wait_group 1;\n" ::: "memory");
        __syncthreads();
        #pragma unroll
        for (int ti = 0; ti < 16; ti++){
            const float* st = &ring[(((g << 4) + ti) & 31) << 8];
            const ull vd = dup(st[192 + mg]);
            ulonglong2 ra = *(const ulonglong2*)&st[nb];
            ulonglong2 ka = *(const ulonglong2*)&st[64 + nb];
            ulonglong2 wa = *(const ulonglong2*)&st[128 + nb];
            ull y0 = 0ull, y1 = 0ull;
            {
                ull a2 = mul2(ka.x, vd);
                ull t2 = fma2(ud, a2, s2[0]);
                y0 = fma2(ra.x, t2, y0);
                s2[0] = fma2(wa.x, s2[0], a2);
            }
            {
                ull a2 = mul2(ka.y, vd);
                ull t2 = fma2(ud, a2, s2[1]);
                y1 = fma2(ra.y, t2, y1);
                s2[1] = fma2(wa.y, s2[1], a2);
            }
            float2 f0 = up2(y0), f1 = up2(y1);
            partial[ti*512 + q*32 + lm] = (f0.x + f0.y) + (f1.x + f1.y);
        }
        __syncthreads();
        {
            const int s = tid >> 5, lm2 = tid & 31;   // 16 steps x 32 m = 512
            float y = 0.f;
            #pragma unroll
            for (int q2 = 0; q2 < 16; q2++) y += partial[s*512 + q2*32 + lm2];
            out[obase + (size_t)((g << 4) + s)*CC + lm2] = y;
        }
        if (g + 2 < TT/16) stage(g + 2);
        else               cpa_commit();
    }
}

// =====================================================================
extern "C" void kernel_launch(void* const* d_in, const int* in_sizes, int n_in,
                              void* d_out, int out_size) {
    const float* hidden  = (const float*)d_in[0];
    const float* attn_x  = (const float*)d_in[1];
    const float* attn_kv = (const float*)d_in[2];
    const float* maa_x   = (const float*)d_in[4];
    const float* maa_w   = (const float*)d_in[5];
    const float* maa_k   = (const float*)d_in[6];
    const float* maa_v   = (const float*)d_in[7];
    const float* maa_r   = (const float*)d_in[8];
    const float* w1      = (const float*)d_in[10];
    const float* w2      = (const float*)d_in[11];
    const float* tdecay  = (const float*)d_in[12];
    const float* dw1     = (const float*)d_in[13];
    const float* dw2     = (const float*)d_in[14];
    const float* faaaa   = (const float*)d_in[15];
    float* out = (float*)d_out;

    static bool attr_set = false;
    if (!attr_set){
        cudaFuncSetAttribute(k_fused, cudaFuncAttributeMaxDynamicSharedMemorySize, SMEM_BYTES);
        cudaFuncSetAttribute(k_scan,  cudaFuncAttributeMaxDynamicSharedMemorySize, SCAN_SMEM_BYTES);
        attr_set = true;
    }

    k_fused<<<NT/64, 512, SMEM_BYTES>>>(hidden, attn_x, maa_x, maa_w, maa_k,
                                        maa_v, maa_r, w1, w2, dw1, dw2, tdecay);
    k_scan <<<128, 512, SCAN_SMEM_BYTES>>>(attn_kv, faaaa, out);
}

// round 11
// speedup vs baseline: 1.3306x; 1.3306x over previous
#include <cuda_runtime.h>
#include <cstdint>

#define BB 2
#define TT 4096
#define CC 2048
#define NT (BB*TT)   // 8192 tokens

typedef unsigned long long ull;

// interleaved scan input: [tok][h][f][64], f: 0=r, 1=k, 2=wd, 3=v  (256MB)
__device__ float g_seq[(size_t)NT*32*4*64];

// ---------------- packed f32x2 helpers ----------------
__device__ __forceinline__ ull pk(float lo, float hi){
    ull r; asm("mov.b64 %0,{%1,%2};" : "=l"(r) : "f"(lo), "f"(hi)); return r;
}
__device__ __forceinline__ ull dup(float x){
    ull r; asm("mov.b64 %0,{%1,%1};" : "=l"(r) : "f"(x)); return r;
}
__device__ __forceinline__ float2 up2(ull a){
    float2 f; asm("mov.b64 {%0,%1},%2;" : "=f"(f.x), "=f"(f.y) : "l"(a)); return f;
}
__device__ __forceinline__ ull fma2(ull a, ull b, ull c){
    ull d; asm("fma.rn.f32x2 %0,%1,%2,%3;" : "=l"(d) : "l"(a), "l"(b), "l"(c)); return d;
}
__device__ __forceinline__ ull mul2(ull a, ull b){
    ull d; asm("mul.rn.f32x2 %0,%1,%2;" : "=l"(d) : "l"(a), "l"(b)); return d;
}
__device__ __forceinline__ ull add2(ull a, ull b){
    ull d; asm("add.rn.f32x2 %0,%1,%2;" : "=l"(d) : "l"(a), "l"(b)); return d;
}
__device__ __forceinline__ void cpa16(uint32_t dst, const void* src){
    asm volatile("cp.async.cg.shared.global [%0],[%1],16;\n" :: "r"(dst), "l"(src) : "memory");
}
__device__ __forceinline__ void cpa_commit(){
    asm volatile("cp.async.commit_group;\n" ::: "memory");
}
__device__ __forceinline__ void cpa_wait0(){
    asm volatile("cp.async.wait_group 0;\n" ::: "memory");
}

// ---------------- k_fused shared layout (float offsets) ----------------
#define OFF_XXX 0            // [64][128]     8192
#define OFF_W2  8192         // [128][128]   16384  -> 24576
#define OFF_DW1 24576        // 2 x [128][68] 17408 -> 41984
#define OFF_XW  41984        // [64][132]     8448  -> 50432
#define OFF_A   50432        // [32][68]      2176  -> 52608
#define OFF_B   52608        // [32][128]     4096  -> 56704
// phase C reuse: D1 at 0 ([64][68] 4352), DW2 at 8192 ([64][128] 8192)
#define SMEM_F 56704
#define SMEM_BYTES (SMEM_F*4)

// =====================================================================
// k_fused: token-shift mix + decay LoRA. 64 tokens/block, 256 threads,
// grid 128. tx = tid&15 (8 output cols), ty = tid>>4 (4 tokens).
// (exact R5 version — measured ~586us)
// =====================================================================
__global__ __launch_bounds__(256, 1) void k_fused(
    const float* __restrict__ hidden, const float* __restrict__ attn_x,
    const float* __restrict__ maa_x,  const float* __restrict__ maa_w,
    const float* __restrict__ maa_k,  const float* __restrict__ maa_v,
    const float* __restrict__ maa_r,  const float* __restrict__ w1,
    const float* __restrict__ w2,     const float* __restrict__ dw1,
    const float* __restrict__ dw2,    const float* __restrict__ tdecay)
{
    extern __shared__ float sm[];
    const int tid = threadIdx.x;
    const int tx = tid & 15, ty = tid >> 4;
    const int bt0 = blockIdx.x * 64;

    const uint32_t smb = (uint32_t)__cvta_generic_to_shared(sm);

    // stage w2 + dw1 chunk via cp.async (one commit group)
    auto stage_wd = [&](int c0, int buf){
        #pragma unroll
        for (int l = 0; l < 16; l++){
            int i = tid + l*256;                // 0..4095 float4s
            int row = i >> 5, c4 = i & 31;
            cpa16(smb + (uint32_t)(OFF_W2 + row*128 + c4*4)*4u,
                  w2 + (size_t)row*CC + c0 + c4*4);
        }
        #pragma unroll
        for (int l = 0; l < 8; l++){
            int i = tid + l*256;                // 0..2047 float4s
            int row = i >> 4, c4 = i & 15;
            cpa16(smb + (uint32_t)(OFF_DW1 + buf*8704 + row*68 + c4*4)*4u,
                  dw1 + (size_t)(c0 + row)*64 + c4*4);
        }
        cpa_commit();
    };

    stage_wd(0, 0);

    // ================= Phase A: xxx = tanh(z @ W1[:,:128]) =================
    {
        float* As = sm + OFF_A;
        float* Bs = sm + OFF_B;
        float rx[8], rp[8], rm[8], rb[16];

        auto prefA = [&](int kc){
            #pragma unroll
            for (int l = 0; l < 8; l++){
                int i = tid + l*256; int kk = i & 31, tl = i >> 5;
                int tok = bt0 + tl; int c = kc + kk;
                rx[l] = hidden[(size_t)tok*CC + c];
                rp[l] = ((tok & (TT-1)) == 0) ? attn_x[(size_t)(tok >> 12)*CC + c]
                                              : hidden[(size_t)(tok-1)*CC + c];
                rm[l] = maa_x[c];
            }
            #pragma unroll
            for (int l = 0; l < 16; l++){
                int i = tid + l*256; int kk = i >> 7, n = i & 127;
                rb[l] = w1[(size_t)(kc+kk)*160 + n];
            }
        };

        ull acc[4][4];
        #pragma unroll
        for (int i = 0; i < 4; i++)
            #pragma unroll
            for (int j = 0; j < 4; j++) acc[i][j] = 0ull;

        prefA(0);
        for (int kc = 0; kc < CC; kc += 32){
            #pragma unroll
            for (int l = 0; l < 8; l++){
                int i = tid + l*256; int kk = i & 31, tl = i >> 5;
                As[kk*68 + tl] = rx[l] + (rp[l] - rx[l])*rm[l];
            }
            #pragma unroll
            for (int l = 0; l < 16; l++){
                int i = tid + l*256; int kk = i >> 7, n = i & 127;
                Bs[kk*128 + n] = rb[l];
            }
            __syncthreads();
            if (kc + 32 < CC) prefA(kc + 32);
            #pragma unroll
            for (int kk = 0; kk < 32; kk++){
                float4 av = *(const float4*)&As[kk*68 + ty*4];
                ulonglong2 b01 = *(const ulonglong2*)&Bs[kk*128 + tx*8];
                ulonglong2 b23 = *(const ulonglong2*)&Bs[kk*128 + tx*8 + 4];
                ull bp[4] = {b01.x, b01.y, b23.x, b23.y};
                float aa[4] = {av.x, av.y, av.z, av.w};
                #pragma unroll
                for (int i = 0; i < 4; i++){
                    ull ad = dup(aa[i]);
                    #pragma unroll
                    for (int j = 0; j < 4; j++) acc[i][j] = fma2(ad, bp[j], acc[i][j]);
                }
            }
            __syncthreads();
        }
        #pragma unroll
        for (int i = 0; i < 4; i++){
            #pragma unroll
            for (int jp = 0; jp < 4; jp++){
                float2 f = up2(acc[i][jp]);
                int r = (ty*4 + i)*128 + tx*8 + 2*jp;
                sm[OFF_XXX + r]   = tanhf(f.x);
                sm[OFF_XXX + r+1] = tanhf(f.y);
            }
        }
    }

    // ================= Phase B =================
    float* xxx_s = sm + OFF_XXX;
    float* w2_s  = sm + OFF_W2;
    float* xw_s  = sm + OFF_XW;

    ull acc_d1[4][2];
    #pragma unroll
    for (int i = 0; i < 4; i++){ acc_d1[i][0] = 0ull; acc_d1[i][1] = 0ull; }

    for (int c0 = 0; c0 < CC; c0 += 128){
        const int cbuf = (c0 >> 7) & 1;
        cpa_wait0();
        __syncthreads();           // w2/dw1 ready; also covers xxx after phase A

        const int cb = c0 + tx*8;
        const int hh = cb >> 6, lmm = cb & 63;

        // x / diff operands -> registers
        float xr[4][8], dr[4][8];
        #pragma unroll
        for (int i = 0; i < 4; i++){
            const int tok = bt0 + ty*4 + i;
            const size_t gofs = (size_t)tok*CC + cb;
            float4 xa = *(const float4*)&hidden[gofs];
            float4 xb = *(const float4*)&hidden[gofs + 4];
            const float* prow = ((tok & (TT-1)) == 0) ? (attn_x + (size_t)(tok >> 12)*CC)
                                                      : (hidden + (size_t)(tok-1)*CC);
            float4 pa = *(const float4*)&prow[cb];
            float4 pb = *(const float4*)&prow[cb + 4];
            xr[i][0]=xa.x; xr[i][1]=xa.y; xr[i][2]=xa.z; xr[i][3]=xa.w;
            xr[i][4]=xb.x; xr[i][5]=xb.y; xr[i][6]=xb.z; xr[i][7]=xb.w;
            dr[i][0]=pa.x-xa.x; dr[i][1]=pa.y-xa.y; dr[i][2]=pa.z-xa.z; dr[i][3]=pa.w-xa.w;
            dr[i][4]=pb.x-xb.x; dr[i][5]=pb.y-xb.y; dr[i][6]=pb.z-xb.z; dr[i][7]=pb.w-xb.w;
        }

        #pragma unroll
        for (int f = 0; f < 4; f++){
            ull macc[4][4];
            #pragma unroll
            for (int i = 0; i < 4; i++)
                #pragma unroll
                for (int j = 0; j < 4; j++) macc[i][j] = 0ull;

            #pragma unroll
            for (int kk = 0; kk < 32; kk++){
                ulonglong2 wa = *(const ulonglong2*)&w2_s[(f*32+kk)*128 + tx*8];
                ulonglong2 wb = *(const ulonglong2*)&w2_s[(f*32+kk)*128 + tx*8 + 4];
                ull bp[4] = {wa.x, wa.y, wb.x, wb.y};
                #pragma unroll
                for (int i = 0; i < 4; i++){
                    ull ad = dup(xxx_s[(ty*4 + i)*128 + f*32 + kk]);
                    #pragma unroll
                    for (int j = 0; j < 4; j++) macc[i][j] = fma2(ad, bp[j], macc[i][j]);
                }
            }
            const float* maaf = (f==0) ? maa_w : (f==1) ? maa_k : (f==2) ? maa_v : maa_r;
            float4 ma = *(const float4*)&maaf[cb];
            float4 mb = *(const float4*)&maaf[cb + 4];
            float mmv[8] = {ma.x,ma.y,ma.z,ma.w,mb.x,mb.y,mb.z,mb.w};
            const int slot = (f==1) ? 1 : (f==2) ? 3 : 0;
            #pragma unroll
            for (int i = 0; i < 4; i++){
                const int tl = ty*4 + i;
                float mq[8];
                #pragma unroll
                for (int jp = 0; jp < 4; jp++){
                    float2 q = up2(macc[i][jp]);
                    mq[2*jp] = q.x; mq[2*jp+1] = q.y;
                }
                float o[8];
                #pragma unroll
                for (int e = 0; e < 8; e++) o[e] = xr[i][e] + dr[i][e]*(mmv[e] + mq[e]);
                if (f == 0){
                    *(float4*)&xw_s[tl*132 + tx*8]     = make_float4(o[0],o[1],o[2],o[3]);
                    *(float4*)&xw_s[tl*132 + tx*8 + 4] = make_float4(o[4],o[5],o[6],o[7]);
                } else {
                    float* dst = &g_seq[((size_t)(bt0 + tl)*32 + hh)*256 + slot*64 + lmm];
                    *(float4*)&dst[0] = make_float4(o[0],o[1],o[2],o[3]);
                    *(float4*)&dst[4] = make_float4(o[4],o[5],o[6],o[7]);
                }
            }
        }
        __syncthreads();           // xw_s complete; w2/dw1 fully consumed

        if (c0 + 128 < CC) stage_wd(c0 + 128, cbuf ^ 1);
        else               cpa_commit();

        const float* dw1c = sm + OFF_DW1 + cbuf*8704;
        #pragma unroll 2
        for (int kk = 0; kk < 128; kk++){
            ulonglong2 bp = *(const ulonglong2*)&dw1c[kk*68 + tx*4];
            #pragma unroll
            for (int i = 0; i < 4; i++){
                ull ad = dup(xw_s[(ty*4 + i)*132 + kk]);
                acc_d1[i][0] = fma2(ad, bp.x, acc_d1[i][0]);
                acc_d1[i][1] = fma2(ad, bp.y, acc_d1[i][1]);
            }
        }
    }
    cpa_wait0();
    __syncthreads();

    // ================= Phase C: wd = exp(-exp(td + tanh(d1) @ dw2)) =================
    float* d1_s  = sm;             // [64][68]
    float* dw2_s = sm + 8192;      // [64][128]
    #pragma unroll
    for (int i = 0; i < 4; i++){
        float2 e0 = up2(acc_d1[i][0]);
        float2 e1 = up2(acc_d1[i][1]);
        int r = (ty*4 + i)*68 + tx*4;
        d1_s[r]   = tanhf(e0.x);
        d1_s[r+1] = tanhf(e0.y);
        d1_s[r+2] = tanhf(e1.x);
        d1_s[r+3] = tanhf(e1.y);
    }
    __syncthreads();

    for (int c0 = 0; c0 < CC; c0 += 128){
        #pragma unroll
        for (int l = 0; l < 32; l++){
            int i = tid + l*256;
            dw2_s[i] = dw2[(size_t)(i >> 7)*CC + c0 + (i & 127)];
        }
        __syncthreads();
        ull wacc[4][4];
        #pragma unroll
        for (int i = 0; i < 4; i++)
            #pragma unroll
            for (int j = 0; j < 4; j++) wacc[i][j] = 0ull;
        #pragma unroll 4
        for (int jj = 0; jj < 64; jj++){
            ulonglong2 wa = *(const ulonglong2*)&dw2_s[jj*128 + tx*8];
            ulonglong2 wb = *(const ulonglong2*)&dw2_s[jj*128 + tx*8 + 4];
            #pragma unroll
            for (int i = 0; i < 4; i++){
                ull ad = dup(d1_s[(ty*4 + i)*68 + jj]);
                wacc[i][0] = fma2(ad, wa.x, wacc[i][0]);
                wacc[i][1] = fma2(ad, wa.y, wacc[i][1]);
                wacc[i][2] = fma2(ad, wb.x, wacc[i][2]);
                wacc[i][3] = fma2(ad, wb.y, wacc[i][3]);
            }
        }
        const int cb = c0 + tx*8;
        const int hh = cb >> 6, lmm = cb & 63;
        float4 t0 = *(const float4*)&tdecay[cb];
        float4 t1 = *(const float4*)&tdecay[cb + 4];
        float td[8] = {t0.x,t0.y,t0.z,t0.w,t1.x,t1.y,t1.z,t1.w};
        #pragma unroll
        for (int i = 0; i < 4; i++){
            const int tl = ty*4 + i;
            float mq[8];
            #pragma unroll
            for (int jp = 0; jp < 4; jp++){
                float2 q = up2(wacc[i][jp]);
                mq[2*jp] = q.x; mq[2*jp+1] = q.y;
            }
            float o[8];
            #pragma unroll
            for (int e = 0; e < 8; e++) o[e] = expf(-expf(td[e] + mq[e]));
            float* dst = &g_seq[((size_t)(bt0 + tl)*32 + hh)*256 + 128 + lmm];
            *(float4*)&dst[0] = make_float4(o[0],o[1],o[2],o[3]);
            *(float4*)&dst[4] = make_float4(o[4],o[5],o[6],o[7]);
        }
        __syncthreads();
    }
}

// =====================================================================
// k_scan: 128 blocks = (b, h, m-half). 512 threads:
//   lm = tid&31 (m within half), q = tid>>5 (16 n-quartets). 2 f32x2
//   state pairs/thread. Ring 32 steps, groups of 16.
//   Per-step partial stored PACKED (add.f32x2 + STS.64); reducer unpacks
//   once per 16 steps with packed accumulation.
// =====================================================================
#define SCAN_SMEM_BYTES (32*256*4 + 16*512*8)   // ring 32KB + packed partial 64KB

__global__ __launch_bounds__(512) void k_scan(
    const float* __restrict__ attn_kv, const float* __restrict__ faaaa,
    float* __restrict__ out)
{
    extern __shared__ float ssm[];
    float* ring   = ssm;                       // [32][256]
    ull* partial2 = (ull*)(ssm + 32*256);      // [16][512] packed

    const int tid = threadIdx.x;
    const int bid = blockIdx.x;
    const int b = bid >> 6, h = (bid >> 1) & 31, half = bid & 1;
    const int lm = tid & 31, q = tid >> 5;        // q in 0..15
    const int mg = half*32 + lm;

    const ull ud = dup(faaaa[h]);

    ull s2[2];
    const float* kvp = attn_kv + ((size_t)(b*32 + h))*4096;
    #pragma unroll
    for (int j = 0; j < 2; j++){
        int n0 = q*4 + 2*j;
        s2[j] = pk(kvp[n0*64 + mg], kvp[(n0+1)*64 + mg]);
    }

    const float4* srcb = (const float4*)g_seq + ((size_t)b*TT)*2048 + h*64;
    const uint32_t rbase = (uint32_t)__cvta_generic_to_shared(ring);

    // stage one 16-step group: 1024 float4s / 512 threads = 2 each
    auto stage = [&](int g16){
        #pragma unroll
        for (int l = 0; l < 2; l++){
            int i = tid + l*512;              // 0..1023
            int t = g16*16 + (i >> 6), o = i & 63;
            cpa16(rbase + (uint32_t)((t & 31)*1024 + o*16), srcb + (size_t)t*2048 + o);
        }
        cpa_commit();
    };

    stage(0);
    stage(1);

    const size_t obase = (size_t)b*TT*CC + h*64 + half*32;
    const int nb = q*4;

    for (int g = 0; g < TT/16; g++){
        asm volatile("cp.async.wait_group 1;\n" ::: "memory");
        __syncthreads();
        #pragma unroll
        for (int ti = 0; ti < 16; ti++){
            const float* st = &ring[(((g << 4) + ti) & 31) << 8];
            const ull vd = dup(st[192 + mg]);
            ulonglong2 ra = *(const ulonglong2*)&st[nb];
            ulonglong2 ka = *(const ulonglong2*)&st[64 + nb];
            ulonglong2 wa = *(const ulonglong2*)&st[128 + nb];
            ull y0, y1;
            {
                ull a2 = mul2(ka.x, vd);
                ull t2 = fma2(ud, a2, s2[0]);
                y0 = mul2(ra.x, t2);
                s2[0] = fma2(wa.x, s2[0], a2);
            }
            {
                ull a2 = mul2(ka.y, vd);
                ull t2 = fma2(ud, a2, s2[1]);
                y1 = mul2(ra.y, t2);
                s2[1] = fma2(wa.y, s2[1], a2);
            }
            partial2[ti*512 + tid] = add2(y0, y1);   // packed partial, STS.64
        }
        __syncthreads();
        {
            const int s = tid >> 5, lm2 = tid & 31;   // 16 steps x 32 m = 512
            ull acc = 0ull;
            #pragma unroll
            for (int q2 = 0; q2 < 16; q2++)
                acc = add2(acc, partial2[s*512 + q2*32 + lm2]);
            float2 fa = up2(acc);
            out[obase + (size_t)((g << 4) + s)*CC + lm2] = fa.x + fa.y;
        }
        if (g + 2 < TT/16) stage(g + 2);
        else               cpa_commit();
    }
}

// =====================================================================
extern "C" void kernel_launch(void* const* d_in, const int* in_sizes, int n_in,
                              void* d_out, int out_size) {
    const float* hidden  = (const float*)d_in[0];
    const float* attn_x  = (const float*)d_in[1];
    const float* attn_kv = (const float*)d_in[2];
    const float* maa_x   = (const float*)d_in[4];
    const float* maa_w   = (const float*)d_in[5];
    const float* maa_k   = (const float*)d_in[6];
    const float* maa_v   = (const float*)d_in[7];
    const float* maa_r   = (const float*)d_in[8];
    const float* w1      = (const float*)d_in[10];
    const float* w2      = (const float*)d_in[11];
    const float* tdecay  = (const float*)d_in[12];
    const float* dw1     = (const float*)d_in[13];
    const float* dw2     = (const float*)d_in[14];
    const float* faaaa   = (const float*)d_in[15];
    float* out = (float*)d_out;

    static bool attr_set = false;
    if (!attr_set){
        cudaFuncSetAttribute(k_fused, cudaFuncAttributeMaxDynamicSharedMemorySize, SMEM_BYTES);
        cudaFuncSetAttribute(k_scan,  cudaFuncAttributeMaxDynamicSharedMemorySize, SCAN_SMEM_BYTES);
        attr_set = true;
    }

    k_fused<<<NT/64, 256, SMEM_BYTES>>>(hidden, attn_x, maa_x, maa_w, maa_k,
                                        maa_v, maa_r, w1, w2, dw1, dw2, tdecay);
    k_scan <<<128, 512, SCAN_SMEM_BYTES>>>(attn_kv, faaaa, out);
}